// round 14
// baseline (speedup 1.0000x reference)
#include <cuda_runtime.h>
#include <cstdint>

#define NMAX 100000
#define EMAX 1250000
#define DEG_CAP 64
#define NSM 148

// Scratch (device globals -- no allocation allowed anywhere).
__device__ float g_agg [NMAX * 64];     // layer-1 neighbor mean
__device__ float g_h1  [NMAX * 64];
__device__ float g_hw2 [NMAX * 32];
__device__ float g_agg2[NMAX * 32];     // layer-2 neighbor mean
__device__ int   g_cnt [NMAX];
__device__ int   g_col [NMAX * DEG_CAP];
__device__ int   g_is64;

__device__ __forceinline__ uint32_t f2tf32(float f) {
    uint32_t u;
    asm("cvt.rna.tf32.f32 %0, %1;" : "=r"(u) : "f"(f));
    return u;
}

__device__ __forceinline__ uint32_t smem_u32(const void* p) {
    uint32_t a;
    asm("{ .reg .u64 t; cvta.to.shared.u64 t, %1; cvt.u32.u64 %0, t; }"
        : "=r"(a) : "l"(p));
    return a;
}

__device__ __forceinline__ void cp16(uint32_t dst, const void* src, int sz) {
    asm volatile("cp.async.cg.shared.global [%0], [%1], 16, %2;"
                 :: "r"(dst), "l"(src), "r"(sz) : "memory");
}

__device__ __forceinline__ void mma16n8k8(float& c0, float& c1, float& c2,
                                          float& c3, uint32_t a0, uint32_t a1,
                                          uint32_t a2, uint32_t a3, uint32_t b0,
                                          uint32_t b1) {
    asm volatile(
        "mma.sync.aligned.m16n8k8.row.col.f32.tf32.tf32.f32 "
        "{%0,%1,%2,%3}, {%4,%5,%6,%7}, {%8,%9}, {%0,%1,%2,%3};"
        : "+f"(c0), "+f"(c1), "+f"(c2), "+f"(c3)
        : "r"(a0), "r"(a1), "r"(a2), "r"(a3), "r"(b0), "r"(b1));
}

__device__ __forceinline__ int load_idx(const void* p, int i, int is64) {
    return is64 ? (int)((const long long*)p)[i] : ((const int*)p)[i];
}

// ---------------------------------------------------------------------------
// Prep: zero counts; block 0 detects index dtype (int32 vs int64).
// ---------------------------------------------------------------------------
__global__ void k_prep(const long long* __restrict__ src64,
                       const long long* __restrict__ dst64, int E, int N) {
    int i = blockIdx.x * blockDim.x + threadIdx.x;
    if (i < N) g_cnt[i] = 0;
    if (blockIdx.x == 0) {
        __shared__ int sBad;
        if (threadIdx.x == 0) sBad = 0;
        __syncthreads();
        int cnt = E < 4096 ? E : 4096;
        int bad = 0;
        for (int j = threadIdx.x; j < cnt; j += blockDim.x) {
            long long a = src64[j], b = dst64[j];
            if (a < 0 || a >= N || b < 0 || b >= N) bad = 1;
        }
        if (bad) atomicOr(&sBad, 1);
        __syncthreads();
        if (threadIdx.x == 0) g_is64 = (sBad == 0) ? 1 : 0;
    }
}

// ---------------------------------------------------------------------------
// Bucketed adjacency fill.
// ---------------------------------------------------------------------------
__global__ void k_fill(const void* __restrict__ src,
                       const void* __restrict__ dst, int E) {
    int e = blockIdx.x * blockDim.x + threadIdx.x;
    if (e >= E) return;
    int is64 = g_is64;
    int s = load_idx(src, e, is64);
    int d = load_idx(dst, e, is64);
    int pos = atomicAdd(&g_cnt[d], 1);
    if (pos < DEG_CAP) g_col[d * DEG_CAP + pos] = s;
}

// ---------------------------------------------------------------------------
// Layer-1 gather: warp per node, lane = float2 chunk; zero smem, max occ.
// ---------------------------------------------------------------------------
__global__ __launch_bounds__(256) void k_agg1(const float* __restrict__ x,
                                              int N) {
    int w    = (blockIdx.x * blockDim.x + threadIdx.x) >> 5;
    int lane = threadIdx.x & 31;
    if (w >= N) return;
    int cntT = g_cnt[w];
    int cnt  = cntT < DEG_CAP ? cntT : DEG_CAP;
    float inv = 1.0f / fmaxf((float)cntT, 1.0f);
    const int4* idx4 = (const int4*)(g_col + w * DEG_CAP);
    float2 a0 = make_float2(0.f, 0.f), a1 = make_float2(0.f, 0.f);
    float2 a2 = make_float2(0.f, 0.f), a3 = make_float2(0.f, 0.f);
    int e = 0;
    for (; e + 4 <= cnt; e += 4) {
        int4 s4 = idx4[e >> 2];
        float2 v0 = ((const float2*)(x + (size_t)s4.x * 64))[lane];
        float2 v1 = ((const float2*)(x + (size_t)s4.y * 64))[lane];
        float2 v2 = ((const float2*)(x + (size_t)s4.z * 64))[lane];
        float2 v3 = ((const float2*)(x + (size_t)s4.w * 64))[lane];
        a0.x += v0.x; a0.y += v0.y;
        a1.x += v1.x; a1.y += v1.y;
        a2.x += v2.x; a2.y += v2.y;
        a3.x += v3.x; a3.y += v3.y;
    }
    if (e < cnt) {
        int4 s4 = idx4[e >> 2];
        int rem = cnt - e;
        float2 v0 = ((const float2*)(x + (size_t)s4.x * 64))[lane];
        a0.x += v0.x; a0.y += v0.y;
        if (rem > 1) {
            float2 v1 = ((const float2*)(x + (size_t)s4.y * 64))[lane];
            a1.x += v1.x; a1.y += v1.y;
        }
        if (rem > 2) {
            float2 v2 = ((const float2*)(x + (size_t)s4.z * 64))[lane];
            a2.x += v2.x; a2.y += v2.y;
        }
    }
    float2 r;
    r.x = ((a0.x + a1.x) + (a2.x + a3.x)) * inv;
    r.y = ((a0.y + a1.y) + (a2.y + a3.y)) * inv;
    ((float2*)(g_agg + (size_t)w * 64))[lane] = r;
}

// ---------------------------------------------------------------------------
// Layer-2 gather: warp per node, lane = feature; zero smem.
// ---------------------------------------------------------------------------
__global__ __launch_bounds__(256) void k_agg2(int N) {
    int w    = (blockIdx.x * blockDim.x + threadIdx.x) >> 5;
    int lane = threadIdx.x & 31;
    if (w >= N) return;
    int cntT = g_cnt[w];
    int cnt  = cntT < DEG_CAP ? cntT : DEG_CAP;
    float inv = 1.0f / fmaxf((float)cntT, 1.0f);
    const int4* idx4 = (const int4*)(g_col + w * DEG_CAP);
    float a0 = 0.f, a1 = 0.f, a2 = 0.f, a3 = 0.f;
    int e = 0;
    for (; e + 4 <= cnt; e += 4) {
        int4 s4 = idx4[e >> 2];
        a0 += g_hw2[(size_t)s4.x * 32 + lane];
        a1 += g_hw2[(size_t)s4.y * 32 + lane];
        a2 += g_hw2[(size_t)s4.z * 32 + lane];
        a3 += g_hw2[(size_t)s4.w * 32 + lane];
    }
    if (e < cnt) {
        int4 s4 = idx4[e >> 2];
        int rem = cnt - e;
        a0 += g_hw2[(size_t)s4.x * 32 + lane];
        if (rem > 1) a1 += g_hw2[(size_t)s4.y * 32 + lane];
        if (rem > 2) a2 += g_hw2[(size_t)s4.z * 32 + lane];
    }
    g_agg2[(size_t)w * 32 + lane] = ((a0 + a1) + (a2 + a3)) * inv;
}

// ---------------------------------------------------------------------------
// Persistent, double-buffered layer-1 GEMM via mma.sync tf32 + cp.async.
// 512 threads, 1 CTA/SM, grid <= 148; weights staged once per block.
//   A[64][128] = [x | g_agg] (raw fp32 bits; HMMA reads tf32 subset)
//   D = A @ [Ws1;Wn1]; h1 = relu(D+b1) -> g_h1; hw2 = h1 @ Wn2 -> g_hw2.
// SMEM: Abuf[2][64*140] + Wt[64*140] + W2[2048] + bias[64] = 115,968 B.
// ---------------------------------------------------------------------------
#define ASTR 140
#define ABUF_FLOATS (64 * ASTR)
#define L1_SMEM ((2 * ABUF_FLOATS + ABUF_FLOATS + 2048 + 64) * 4)

__device__ __forceinline__ void stage_tile(uint32_t bufAddr,
                                           const float* __restrict__ x,
                                           int node0, int N, int tid) {
    for (int i = tid; i < 1024; i += 512) {
        int n = i >> 4, q4 = i & 15;
        int gn = node0 + n;
        int sz = (gn < N) ? 16 : 0;
        int gs = (gn < N) ? gn : 0;
        uint32_t d = bufAddr + (uint32_t)(n * ASTR + q4 * 4) * 4u;
        cp16(d,        x     + (size_t)gs * 64 + q4 * 4, sz);
        cp16(d + 256u, g_agg + (size_t)gs * 64 + q4 * 4, sz);
    }
    asm volatile("cp.async.commit_group;" ::: "memory");
}

__global__ __launch_bounds__(512) void k_mma1(
    const float* __restrict__ x,
    const float* __restrict__ Ws1, const float* __restrict__ Wn1,
    const float* __restrict__ b1,  const float* __restrict__ Wn2,
    int N, int ntiles) {
    extern __shared__ float sm[];
    float* sAb  = sm;                           // [2][64*140]
    float* sWt  = sm + 2 * ABUF_FLOATS;         // [64][140]
    float* sW2  = sm + 3 * ABUF_FLOATS;         // [64][32]
    float* sBias= sm + 3 * ABUF_FLOATS + 2048;  // [64]
    uint32_t* uWt = (uint32_t*)sWt;
    uint32_t sbase = smem_u32(sm);

    int tid = threadIdx.x, warp = tid >> 5, lane = tid & 31;

    // Stage weights ONCE (B kept rna-rounded tf32).
    for (int i = tid; i < 64 * 128; i += 512) {
        int n = i & 63, k = i >> 6;
        float v = (k < 64) ? Ws1[k * 64 + n] : Wn1[(k - 64) * 64 + n];
        uWt[n * ASTR + k] = f2tf32(v);
    }
    for (int i = tid; i < 2048; i += 512) sW2[i] = Wn2[i];
    if (tid < 64) sBias[tid] = b1[tid];

    // MMA mapping: 16 warps -> m0 = (w&3)*16, n0 = (w>>2)*16 (2 n8-tiles).
    int m0 = (warp & 3) * 16;
    int n0 = (warp >> 2) * 16;
    int r = lane >> 2, kq = lane & 3;
    int c = tid & 31, ng = tid >> 5;             // for hw2: 16 node-groups

    int stride = gridDim.x;
    int t0 = blockIdx.x;
    if (t0 < ntiles) stage_tile(sbase, x, t0 * 64, N, tid);

    int par = 0;
    for (int t = t0; t < ntiles; t += stride) {
        uint32_t curAddr = sbase + (uint32_t)(par * ABUF_FLOATS) * 4u;
        uint32_t* uA = (uint32_t*)(sm + par * ABUF_FLOATS);
        float*    sH = sm + par * ABUF_FLOATS;
        int node0 = t * 64;
        int tn = t + stride;

        if (tn < ntiles) {
            stage_tile(sbase + (uint32_t)((par ^ 1) * ABUF_FLOATS) * 4u,
                       x, tn * 64, N, tid);
            asm volatile("cp.async.wait_group 1;" ::: "memory");
        } else {
            asm volatile("cp.async.wait_group 0;" ::: "memory");
        }
        __syncthreads();

        float acc[2][4];
#pragma unroll
        for (int j = 0; j < 2; j++)
            acc[j][0] = acc[j][1] = acc[j][2] = acc[j][3] = 0.f;

#pragma unroll 4
        for (int ks = 0; ks < 16; ks++) {
            int k0 = ks * 8;
            uint32_t a0 = uA[(m0 + r)     * ASTR + k0 + kq];
            uint32_t a1 = uA[(m0 + r + 8) * ASTR + k0 + kq];
            uint32_t a2 = uA[(m0 + r)     * ASTR + k0 + kq + 4];
            uint32_t a3 = uA[(m0 + r + 8) * ASTR + k0 + kq + 4];
#pragma unroll
            for (int j = 0; j < 2; j++) {
                int n = n0 + j * 8;
                uint32_t b0 = uWt[(n + r) * ASTR + k0 + kq];
                uint32_t b1v = uWt[(n + r) * ASTR + k0 + kq + 4];
                mma16n8k8(acc[j][0], acc[j][1], acc[j][2], acc[j][3],
                          a0, a1, a2, a3, b0, b1v);
            }
        }
        __syncthreads();   // MMA reads of uA done before sH overwrite

        // Epilogue: h1 = relu(D + bias) into sH (aliases current A buffer).
#pragma unroll
        for (int j = 0; j < 2; j++) {
            int n = n0 + j * 8 + 2 * kq;
            sH[(m0 + r)     * ASTR + n]     = fmaxf(acc[j][0] + sBias[n],     0.f);
            sH[(m0 + r)     * ASTR + n + 1] = fmaxf(acc[j][1] + sBias[n + 1], 0.f);
            sH[(m0 + r + 8) * ASTR + n]     = fmaxf(acc[j][2] + sBias[n],     0.f);
            sH[(m0 + r + 8) * ASTR + n + 1] = fmaxf(acc[j][3] + sBias[n + 1], 0.f);
        }
        __syncthreads();

        // Writeback h1 (coalesced).
        for (int i = tid; i < 1024; i += 512) {
            int n = i >> 4, q = i & 15;
            int gn = node0 + n;
            if (gn < N)
                *(float4*)&g_h1[(size_t)gn * 64 + q * 4] =
                    *(float4*)&sH[n * ASTR + q * 4];
        }

        // hw2 = h1 @ Wn2 (SIMT): 512 threads, 4 nodes per thread.
        float a2r[4];
#pragma unroll
        for (int i = 0; i < 4; i++) a2r[i] = 0.f;
#pragma unroll 4
        for (int k0 = 0; k0 < 64; k0 += 4) {
            float w0 = sW2[(k0 + 0) * 32 + c];
            float w1 = sW2[(k0 + 1) * 32 + c];
            float w2 = sW2[(k0 + 2) * 32 + c];
            float w3 = sW2[(k0 + 3) * 32 + c];
#pragma unroll
            for (int i = 0; i < 4; i++) {
                float4 hv = *(float4*)&sH[(ng + 16 * i) * ASTR + k0];
                a2r[i] += hv.x * w0 + hv.y * w1 + hv.z * w2 + hv.w * w3;
            }
        }
#pragma unroll
        for (int i = 0; i < 4; i++) {
            int gn = node0 + ng + 16 * i;
            if (gn < N) g_hw2[(size_t)gn * 32 + c] = a2r[i];
        }
        __syncthreads();   // sH reads done before next iter's prefetch lands here
        par ^= 1;
    }
}

// ---------------------------------------------------------------------------
// Persistent final: out = h1 @ Ws2 + g_agg2 + b2. Ws2 staged once.
// ---------------------------------------------------------------------------
__global__ __launch_bounds__(256) void k_final(
    const float* __restrict__ Ws2, const float* __restrict__ b2,
    float* __restrict__ out, int N, int ntiles) {
    __shared__ float sW2T[32 * 68];
    __shared__ float sh  [64 * 68];

    int tid = threadIdx.x;
    for (int i = tid; i < 2048; i += 256) {
        int k = i >> 5, c = i & 31;
        sW2T[c * 68 + k] = Ws2[i];
    }
    int c = tid & 31, ng = tid >> 5;
    float bb = b2[c];

    for (int t = blockIdx.x; t < ntiles; t += gridDim.x) {
        int node0 = t * 64;
        __syncthreads();
        for (int i = tid; i < 64 * 64; i += 256) {
            int n = i >> 6, f = i & 63;
            int gn = node0 + n;
            sh[n * 68 + f] = (gn < N) ? g_h1[(size_t)gn * 64 + f] : 0.f;
        }
        __syncthreads();

        float acc[8];
#pragma unroll
        for (int i = 0; i < 8; i++) acc[i] = 0.f;
#pragma unroll 4
        for (int k0 = 0; k0 < 64; k0 += 4) {
            float4 wv = *(float4*)&sW2T[c * 68 + k0];
#pragma unroll
            for (int i = 0; i < 8; i++) {
                float4 hv = *(float4*)&sh[(ng + 8 * i) * 68 + k0];
                acc[i] += hv.x * wv.x + hv.y * wv.y + hv.z * wv.z + hv.w * wv.w;
            }
        }
#pragma unroll
        for (int i = 0; i < 8; i++) {
            int gn = node0 + ng + 8 * i;
            if (gn < N)
                out[(size_t)gn * 32 + c] =
                    acc[i] + bb + g_agg2[(size_t)gn * 32 + c];
        }
    }
}

// ---------------------------------------------------------------------------
extern "C" void kernel_launch(void* const* d_in, const int* in_sizes, int n_in,
                              void* d_out, int out_size) {
    const float* x   = (const float*)d_in[0];
    const void*  src = d_in[1];
    const void*  dst = d_in[2];
    const float* Ws1 = (const float*)d_in[3];
    const float* Wn1 = (const float*)d_in[4];
    const float* b1  = (const float*)d_in[5];
    const float* Ws2 = (const float*)d_in[6];
    const float* Wn2 = (const float*)d_in[7];
    const float* b2  = (const float*)d_in[8];
    float* out = (float*)d_out;

    int N = in_sizes[0] / 64;
    if (N > NMAX) N = NMAX;
    int E = in_sizes[1];
    if (E > EMAX) E = EMAX;
    int ntiles = (N + 63) / 64;

    int g1 = NSM;     if (g1 > ntiles) g1 = ntiles;
    int g2 = NSM * 4; if (g2 > ntiles) g2 = ntiles;

    cudaFuncSetAttribute(k_mma1, cudaFuncAttributeMaxDynamicSharedMemorySize,
                         L1_SMEM);

    k_prep<<<(N + 255) / 256, 256>>>((const long long*)src,
                                     (const long long*)dst, E, N);
    k_fill<<<(E + 511) / 512, 512>>>(src, dst, E);
    {
        long long threads = (long long)N * 32;
        k_agg1<<<(int)((threads + 255) / 256), 256>>>(x, N);
    }
    k_mma1<<<g1, 512, L1_SMEM>>>(x, Ws1, Wn1, b1, Wn2, N, ntiles);
    {
        long long threads = (long long)N * 32;
        k_agg2<<<(int)((threads + 255) / 256), 256>>>(N);
    }
    k_final<<<g2, 256>>>(Ws2, b2, out, N, ntiles);
}

// round 15
// speedup vs baseline: 1.1647x; 1.1647x over previous
#include <cuda_runtime.h>
#include <cuda_fp16.h>
#include <cstdint>

#define NMAX 100000
#define EMAX 1250000
#define DEG_CAP 64
#define NSM 148

// Scratch (device globals -- no allocation allowed anywhere).
__device__ __half g_xh  [NMAX * 64];    // x in fp16
__device__ __half g_aggh[NMAX * 64];    // layer-1 neighbor mean (fp16)
__device__ float  g_h1  [NMAX * 64];
__device__ __half g_hw2h[NMAX * 32];    // h1 @ Wn2 (fp16)
__device__ float  g_agg2[NMAX * 32];    // layer-2 neighbor mean
__device__ int    g_cnt [NMAX];
__device__ int    g_col [NMAX * DEG_CAP];
__device__ int    g_is64;

__device__ __forceinline__ uint32_t smem_u32(const void* p) {
    uint32_t a;
    asm("{ .reg .u64 t; cvta.to.shared.u64 t, %1; cvt.u32.u64 %0, t; }"
        : "=r"(a) : "l"(p));
    return a;
}

__device__ __forceinline__ void cp16(uint32_t dst, const void* src, int sz) {
    asm volatile("cp.async.cg.shared.global [%0], [%1], 16, %2;"
                 :: "r"(dst), "l"(src), "r"(sz) : "memory");
}

// m16n8k16 fp16 MMA, fp32 accumulate.
__device__ __forceinline__ void mma_f16(float& c0, float& c1, float& c2,
                                        float& c3, uint32_t a0, uint32_t a1,
                                        uint32_t a2, uint32_t a3, uint32_t b0,
                                        uint32_t b1) {
    asm volatile(
        "mma.sync.aligned.m16n8k16.row.col.f32.f16.f16.f32 "
        "{%0,%1,%2,%3}, {%4,%5,%6,%7}, {%8,%9}, {%0,%1,%2,%3};"
        : "+f"(c0), "+f"(c1), "+f"(c2), "+f"(c3)
        : "r"(a0), "r"(a1), "r"(a2), "r"(a3), "r"(b0), "r"(b1));
}

__device__ __forceinline__ int load_idx(const void* p, int i, int is64) {
    return is64 ? (int)((const long long*)p)[i] : ((const int*)p)[i];
}

// ---------------------------------------------------------------------------
// Prep: zero counts; block 0 detects index dtype (int32 vs int64).
// ---------------------------------------------------------------------------
__global__ void k_prep(const long long* __restrict__ src64,
                       const long long* __restrict__ dst64, int E, int N) {
    int i = blockIdx.x * blockDim.x + threadIdx.x;
    if (i < N) g_cnt[i] = 0;
    if (blockIdx.x == 0) {
        __shared__ int sBad;
        if (threadIdx.x == 0) sBad = 0;
        __syncthreads();
        int cnt = E < 4096 ? E : 4096;
        int bad = 0;
        for (int j = threadIdx.x; j < cnt; j += blockDim.x) {
            long long a = src64[j], b = dst64[j];
            if (a < 0 || a >= N || b < 0 || b >= N) bad = 1;
        }
        if (bad) atomicOr(&sBad, 1);
        __syncthreads();
        if (threadIdx.x == 0) g_is64 = (sBad == 0) ? 1 : 0;
    }
}

// ---------------------------------------------------------------------------
// x -> fp16 (round-to-nearest).
// ---------------------------------------------------------------------------
__global__ void k_cvt(const float* __restrict__ x, int N) {
    int i = blockIdx.x * blockDim.x + threadIdx.x;
    if (i < N * 32) {
        float2 v = ((const float2*)x)[i];
        ((__half2*)g_xh)[i] = __floats2half2_rn(v.x, v.y);
    }
}

// ---------------------------------------------------------------------------
// Bucketed adjacency fill.
// ---------------------------------------------------------------------------
__global__ void k_fill(const void* __restrict__ src,
                       const void* __restrict__ dst, int E) {
    int e = blockIdx.x * blockDim.x + threadIdx.x;
    if (e >= E) return;
    int is64 = g_is64;
    int s = load_idx(src, e, is64);
    int d = load_idx(dst, e, is64);
    int pos = atomicAdd(&g_cnt[d], 1);
    if (pos < DEG_CAP) g_col[d * DEG_CAP + pos] = s;
}

// ---------------------------------------------------------------------------
// Layer-1 gather (fp16 rows): warp per node, lane = half2 chunk.
// g_aggh[n] = mean over in-edges of xh[src]. Accumulate fp32.
// ---------------------------------------------------------------------------
__global__ __launch_bounds__(256) void k_agg1(int N) {
    int w    = (blockIdx.x * blockDim.x + threadIdx.x) >> 5;
    int lane = threadIdx.x & 31;
    if (w >= N) return;
    int cntT = g_cnt[w];
    int cnt  = cntT < DEG_CAP ? cntT : DEG_CAP;
    float inv = 1.0f / fmaxf((float)cntT, 1.0f);
    const int4* idx4 = (const int4*)(g_col + w * DEG_CAP);
    const __half2* xh2 = (const __half2*)g_xh;
    float2 a0 = make_float2(0.f, 0.f), a1 = make_float2(0.f, 0.f);
    float2 a2 = make_float2(0.f, 0.f), a3 = make_float2(0.f, 0.f);
    int e = 0;
    for (; e + 4 <= cnt; e += 4) {
        int4 s4 = idx4[e >> 2];
        float2 v0 = __half22float2(xh2[(size_t)s4.x * 32 + lane]);
        float2 v1 = __half22float2(xh2[(size_t)s4.y * 32 + lane]);
        float2 v2 = __half22float2(xh2[(size_t)s4.z * 32 + lane]);
        float2 v3 = __half22float2(xh2[(size_t)s4.w * 32 + lane]);
        a0.x += v0.x; a0.y += v0.y;
        a1.x += v1.x; a1.y += v1.y;
        a2.x += v2.x; a2.y += v2.y;
        a3.x += v3.x; a3.y += v3.y;
    }
    if (e < cnt) {
        int4 s4 = idx4[e >> 2];
        int rem = cnt - e;
        float2 v0 = __half22float2(xh2[(size_t)s4.x * 32 + lane]);
        a0.x += v0.x; a0.y += v0.y;
        if (rem > 1) {
            float2 v1 = __half22float2(xh2[(size_t)s4.y * 32 + lane]);
            a1.x += v1.x; a1.y += v1.y;
        }
        if (rem > 2) {
            float2 v2 = __half22float2(xh2[(size_t)s4.z * 32 + lane]);
            a2.x += v2.x; a2.y += v2.y;
        }
    }
    float rx = ((a0.x + a1.x) + (a2.x + a3.x)) * inv;
    float ry = ((a0.y + a1.y) + (a2.y + a3.y)) * inv;
    ((__half2*)g_aggh)[(size_t)w * 32 + lane] = __floats2half2_rn(rx, ry);
}

// ---------------------------------------------------------------------------
// Layer-2 gather (fp16 rows): warp per node, lane = feature.
// ---------------------------------------------------------------------------
__global__ __launch_bounds__(256) void k_agg2(int N) {
    int w    = (blockIdx.x * blockDim.x + threadIdx.x) >> 5;
    int lane = threadIdx.x & 31;
    if (w >= N) return;
    int cntT = g_cnt[w];
    int cnt  = cntT < DEG_CAP ? cntT : DEG_CAP;
    float inv = 1.0f / fmaxf((float)cntT, 1.0f);
    const int4* idx4 = (const int4*)(g_col + w * DEG_CAP);
    float a0 = 0.f, a1 = 0.f, a2 = 0.f, a3 = 0.f;
    int e = 0;
    for (; e + 4 <= cnt; e += 4) {
        int4 s4 = idx4[e >> 2];
        a0 += __half2float(g_hw2h[(size_t)s4.x * 32 + lane]);
        a1 += __half2float(g_hw2h[(size_t)s4.y * 32 + lane]);
        a2 += __half2float(g_hw2h[(size_t)s4.z * 32 + lane]);
        a3 += __half2float(g_hw2h[(size_t)s4.w * 32 + lane]);
    }
    if (e < cnt) {
        int4 s4 = idx4[e >> 2];
        int rem = cnt - e;
        a0 += __half2float(g_hw2h[(size_t)s4.x * 32 + lane]);
        if (rem > 1) a1 += __half2float(g_hw2h[(size_t)s4.y * 32 + lane]);
        if (rem > 2) a2 += __half2float(g_hw2h[(size_t)s4.z * 32 + lane]);
    }
    g_agg2[(size_t)w * 32 + lane] = ((a0 + a1) + (a2 + a3)) * inv;
}

// ---------------------------------------------------------------------------
// Persistent, double-buffered layer-1 GEMM via mma.sync fp16 (m16n8k16).
// 512 threads, 2 CTAs/SM.
//   A[64][128] = [xh | aggh] (half, stride 136 halves = 272B)
//   D = A @ [Ws1;Wn1] (half); h1 = relu(D+b1) fp32 -> g_h1;
//   hw2 = h1 @ Wn2 -> g_hw2h (half).
// SMEM per CTA: 2 Abuf (2x17408) + Wt (17408) + W2 (8192) + bias (256) = 60672.
// ---------------------------------------------------------------------------
#define ASTRH 136                       // halves per A row (64 row bytes = 272)
#define ABUF_BYTES (64 * ASTRH * 2)     // 17408
#define L1_SMEM (2 * ABUF_BYTES + ABUF_BYTES + 8192 + 256)

__device__ __forceinline__ void stage_tile(uint32_t bufAddr, int node0, int N,
                                           int tid) {
    for (int i = tid; i < 1024; i += 512) {
        int n = i >> 4, q = i & 15;                 // q<8: xh, q>=8: aggh
        int gn = node0 + n;
        int sz = (gn < N) ? 16 : 0;
        int gs = (gn < N) ? gn : 0;
        const __half* s = (q < 8) ? (g_xh   + (size_t)gs * 64 + q * 8)
                                  : (g_aggh + (size_t)gs * 64 + (q - 8) * 8);
        cp16(bufAddr + (uint32_t)(n * 272 + q * 16), s, sz);
    }
    asm volatile("cp.async.commit_group;" ::: "memory");
}

__global__ __launch_bounds__(512) void k_mma1(
    const float* __restrict__ Ws1, const float* __restrict__ Wn1,
    const float* __restrict__ b1,  const float* __restrict__ Wn2,
    int N, int ntiles) {
    extern __shared__ float sm[];
    char*  smc  = (char*)sm;
    __half* sWt = (__half*)(smc + 2 * ABUF_BYTES);  // [64][136] half
    float* sW2  = (float*)(smc + 3 * ABUF_BYTES);   // [64][32]
    float* sBias= (float*)(smc + 3 * ABUF_BYTES + 8192);
    uint32_t* uWt = (uint32_t*)sWt;
    uint32_t sbase = smem_u32(sm);

    int tid = threadIdx.x, warp = tid >> 5, lane = tid & 31;

    // Stage weights ONCE: Wt[n][k] = half(k<64 ? Ws1[k][n] : Wn1[k-64][n]).
    for (int i = tid; i < 64 * 128; i += 512) {
        int n = i & 63, k = i >> 6;
        float v = (k < 64) ? Ws1[k * 64 + n] : Wn1[(k - 64) * 64 + n];
        sWt[n * ASTRH + k] = __float2half_rn(v);
    }
    for (int i = tid; i < 2048; i += 512) sW2[i] = Wn2[i];
    if (tid < 64) sBias[tid] = b1[tid];

    // 16 warps: m0 = (w&3)*16 rows, n0 = (w>>2)*16 cols (2 n8-tiles).
    int m0 = (warp & 3) * 16;
    int n0 = (warp >> 2) * 16;
    int r = lane >> 2, kq = lane & 3;
    int c = tid & 31, ng = tid >> 5;

    int stride = gridDim.x;
    int t0 = blockIdx.x;
    if (t0 < ntiles) stage_tile(sbase, t0 * 64, N, tid);

    int par = 0;
    for (int t = t0; t < ntiles; t += stride) {
        uint32_t* uA = (uint32_t*)(smc + par * ABUF_BYTES);  // half2-packed A
        float*    sH = (float*)(smc + par * ABUF_BYTES);     // [64][68] fp32 alias
        int node0 = t * 64;
        int tn = t + stride;

        if (tn < ntiles) {
            stage_tile(sbase + (uint32_t)((par ^ 1) * ABUF_BYTES),
                       tn * 64, N, tid);
            asm volatile("cp.async.wait_group 1;" ::: "memory");
        } else {
            asm volatile("cp.async.wait_group 0;" ::: "memory");
        }
        __syncthreads();

        float acc[2][4];
#pragma unroll
        for (int j = 0; j < 2; j++)
            acc[j][0] = acc[j][1] = acc[j][2] = acc[j][3] = 0.f;

        // 8 k-steps of 16 halves; u32 index = row*68 + k0h + kq (+4 for hi 8).
#pragma unroll
        for (int ks = 0; ks < 8; ks++) {
            int k0h = ks * 8;
            uint32_t a0 = uA[(m0 + r)     * 68 + k0h + kq];
            uint32_t a1 = uA[(m0 + r + 8) * 68 + k0h + kq];
            uint32_t a2 = uA[(m0 + r)     * 68 + k0h + kq + 4];
            uint32_t a3 = uA[(m0 + r + 8) * 68 + k0h + kq + 4];
#pragma unroll
            for (int j = 0; j < 2; j++) {
                int n = n0 + j * 8;
                uint32_t b0  = uWt[(n + r) * 68 + k0h + kq];
                uint32_t b1v = uWt[(n + r) * 68 + k0h + kq + 4];
                mma_f16(acc[j][0], acc[j][1], acc[j][2], acc[j][3],
                        a0, a1, a2, a3, b0, b1v);
            }
        }
        __syncthreads();   // MMA reads of uA done before sH overwrite

        // Epilogue: h1 = relu(D + bias) into sH (fp32, stride 68).
#pragma unroll
        for (int j = 0; j < 2; j++) {
            int n = n0 + j * 8 + 2 * kq;
            sH[(m0 + r)     * 68 + n]     = fmaxf(acc[j][0] + sBias[n],     0.f);
            sH[(m0 + r)     * 68 + n + 1] = fmaxf(acc[j][1] + sBias[n + 1], 0.f);
            sH[(m0 + r + 8) * 68 + n]     = fmaxf(acc[j][2] + sBias[n],     0.f);
            sH[(m0 + r + 8) * 68 + n + 1] = fmaxf(acc[j][3] + sBias[n + 1], 0.f);
        }
        __syncthreads();

        // Writeback h1 (coalesced fp32).
        for (int i = tid; i < 1024; i += 512) {
            int n = i >> 4, q = i & 15;
            int gn = node0 + n;
            if (gn < N)
                *(float4*)&g_h1[(size_t)gn * 64 + q * 4] =
                    *(float4*)&sH[n * 68 + q * 4];
        }

        // hw2 = h1 @ Wn2 (SIMT), write fp16: 4 nodes per thread.
        float a2r[4];
#pragma unroll
        for (int i = 0; i < 4; i++) a2r[i] = 0.f;
#pragma unroll 4
        for (int k0 = 0; k0 < 64; k0 += 4) {
            float w0 = sW2[(k0 + 0) * 32 + c];
            float w1 = sW2[(k0 + 1) * 32 + c];
            float w2 = sW2[(k0 + 2) * 32 + c];
            float w3 = sW2[(k0 + 3) * 32 + c];
#pragma unroll
            for (int i = 0; i < 4; i++) {
                float4 hv = *(float4*)&sH[(ng + 16 * i) * 68 + k0];
                a2r[i] += hv.x * w0 + hv.y * w1 + hv.z * w2 + hv.w * w3;
            }
        }
#pragma unroll
        for (int i = 0; i < 4; i++) {
            int gn = node0 + ng + 16 * i;
            if (gn < N)
                g_hw2h[(size_t)gn * 32 + c] = __float2half_rn(a2r[i]);
        }
        __syncthreads();   // sH reads done before next prefetch lands here
        par ^= 1;
    }
}

// ---------------------------------------------------------------------------
// Persistent final: out = h1 @ Ws2 + g_agg2 + b2. Ws2 staged once. fp32.
// ---------------------------------------------------------------------------
__global__ __launch_bounds__(256) void k_final(
    const float* __restrict__ Ws2, const float* __restrict__ b2,
    float* __restrict__ out, int N, int ntiles) {
    __shared__ float sW2T[32 * 68];
    __shared__ float sh  [64 * 68];

    int tid = threadIdx.x;
    for (int i = tid; i < 2048; i += 256) {
        int k = i >> 5, c = i & 31;
        sW2T[c * 68 + k] = Ws2[i];
    }
    int c = tid & 31, ng = tid >> 5;
    float bb = b2[c];

    for (int t = blockIdx.x; t < ntiles; t += gridDim.x) {
        int node0 = t * 64;
        __syncthreads();
        for (int i = tid; i < 64 * 64; i += 256) {
            int n = i >> 6, f = i & 63;
            int gn = node0 + n;
            sh[n * 68 + f] = (gn < N) ? g_h1[(size_t)gn * 64 + f] : 0.f;
        }
        __syncthreads();

        float acc[8];
#pragma unroll
        for (int i = 0; i < 8; i++) acc[i] = 0.f;
#pragma unroll 4
        for (int k0 = 0; k0 < 64; k0 += 4) {
            float4 wv = *(float4*)&sW2T[c * 68 + k0];
#pragma unroll
            for (int i = 0; i < 8; i++) {
                float4 hv = *(float4*)&sh[(ng + 8 * i) * 68 + k0];
                acc[i] += hv.x * wv.x + hv.y * wv.y + hv.z * wv.z + hv.w * wv.w;
            }
        }
#pragma unroll
        for (int i = 0; i < 8; i++) {
            int gn = node0 + ng + 8 * i;
            if (gn < N)
                out[(size_t)gn * 32 + c] =
                    acc[i] + bb + g_agg2[(size_t)gn * 32 + c];
        }
    }
}

// ---------------------------------------------------------------------------
extern "C" void kernel_launch(void* const* d_in, const int* in_sizes, int n_in,
                              void* d_out, int out_size) {
    const float* x   = (const float*)d_in[0];
    const void*  src = d_in[1];
    const void*  dst = d_in[2];
    const float* Ws1 = (const float*)d_in[3];
    const float* Wn1 = (const float*)d_in[4];
    const float* b1  = (const float*)d_in[5];
    const float* Ws2 = (const float*)d_in[6];
    const float* Wn2 = (const float*)d_in[7];
    const float* b2  = (const float*)d_in[8];
    float* out = (float*)d_out;

    int N = in_sizes[0] / 64;
    if (N > NMAX) N = NMAX;
    int E = in_sizes[1];
    if (E > EMAX) E = EMAX;
    int ntiles = (N + 63) / 64;

    int g1 = NSM * 2; if (g1 > ntiles) g1 = ntiles;
    int g2 = NSM * 4; if (g2 > ntiles) g2 = ntiles;

    cudaFuncSetAttribute(k_mma1, cudaFuncAttributeMaxDynamicSharedMemorySize,
                         L1_SMEM);

    k_prep<<<(N + 255) / 256, 256>>>((const long long*)src,
                                     (const long long*)dst, E, N);
    k_cvt<<<(N * 32 + 255) / 256, 256>>>(x, N);
    k_fill<<<(E + 511) / 512, 512>>>(src, dst, E);
    {
        long long threads = (long long)N * 32;
        k_agg1<<<(int)((threads + 255) / 256), 256>>>(N);
    }
    k_mma1<<<g1, 512, L1_SMEM>>>(Ws1, Wn1, b1, Wn2, N, ntiles);
    {
        long long threads = (long long)N * 32;
        k_agg2<<<(int)((threads + 255) / 256), 256>>>(N);
    }
    k_final<<<g2, 256>>>(Ws2, b2, out, N, ntiles);
}